// round 4
// baseline (speedup 1.0000x reference)
#include <cuda_runtime.h>

#define Tlen  8192
#define Bsz   4
#define RES   256
#define SKIPC 512
#define NCLSC 256
#define NLAY  30
#define WIN   3072
#define HSTR  3200
#define KT    32

typedef unsigned long long ull;

// ---------------- device scratch (allocation-free) ----------------
__device__ float g_h[2][Bsz][RES][HSTR];       // ping-pong hidden state; pads stay zero
__device__ float g_WdT[NLAY][2 * RES][RES];    // transposed conv weights  [k][co]
__device__ float g_WrT[NLAY][RES][RES];        // transposed residual weights
__device__ float g_gLast[NLAY][Bsz][RES];      // gated activation at t = T-1 per layer
__device__ float g_skip[Bsz][SKIPC];

// ---------------- f32x2 helpers ----------------
__device__ __forceinline__ ull pk2(float v) {
    ull r; asm("mov.b64 %0, {%1,%2};" : "=l"(r) : "f"(v), "f"(v)); return r;
}
__device__ __forceinline__ ull fma2(ull a, ull b, ull c) {
    ull d; asm("fma.rn.f32x2 %0, %1, %2, %3;" : "=l"(d) : "l"(a), "l"(b), "l"(c)); return d;
}
__device__ __forceinline__ float2 upk(ull v) {
    float2 f; asm("mov.b64 {%0,%1}, %2;" : "=f"(f.x), "=f"(f.y) : "l"(v)); return f;
}
__device__ __forceinline__ float gate_fn(float d) {
    float e1 = __expf(-d);
    float sg = __fdividef(1.f, 1.f + e1);
    float th = __fdividef(2.f, 1.f + e1 * e1) - 1.f;
    return th * sg;
}
__device__ __forceinline__ unsigned su32(const void* p) {
    return (unsigned)__cvta_generic_to_shared(p);
}

#define CPA16(d, s) asm volatile("cp.async.cg.shared.global [%0],[%1],16;\n" :: "r"(d), "l"(s))
#define CPA4(d, s)  asm volatile("cp.async.ca.shared.global [%0],[%1],4;\n"  :: "r"(d), "l"(s))
#define CPCOMMIT()  asm volatile("cp.async.commit_group;\n")
#define CPWAIT0()   asm volatile("cp.async.wait_group 0;\n" ::: "memory")

// ---------------- weight transpose prep ----------------
__global__ void transpose_prep(const float* __restrict__ Wd, const float* __restrict__ Wr) {
    __shared__ float t[32][33];
    int z = blockIdx.z;
    int lay = z % NLAY, which = z / NLAY;
    const float* src; float* dst; int K;
    if (which == 0) { K = 512; src = Wd + (size_t)lay * RES * 512; dst = &g_WdT[lay][0][0]; }
    else            { K = 256; src = Wr + (size_t)lay * RES * 256; dst = &g_WrT[lay][0][0];
                      if ((int)blockIdx.x >= K / 32) return; }
    int k0 = blockIdx.x * 32, c0 = blockIdx.y * 32;
    int tx = threadIdx.x, ty = threadIdx.y;
    for (int j = 0; j < 32; j += 8)
        t[ty + j][tx] = src[(size_t)(c0 + ty + j) * K + k0 + tx];
    __syncthreads();
    for (int j = 0; j < 32; j += 8)
        dst[(size_t)(k0 + ty + j) * RES + c0 + tx] = t[tx][ty + j];
}

// ---------------- start conv ----------------
__global__ void start_conv(const float* __restrict__ x,
                           const float* __restrict__ Wst,
                           const float* __restrict__ bst) {
    int b = blockIdx.y;
    int u = blockIdx.x * 256 + threadIdx.x;
    int t = (Tlen - WIN) + u;
    float x0 = x[b * Tlen + t - 1];
    float x1 = x[b * Tlen + t];
    for (int c = 0; c < RES; c++)
        g_h[0][b][c][u] = bst[c] + Wst[2 * c] * x0 + Wst[2 * c + 1] * x1;
}

// ---------------- fused layer kernel ----------------
// TPB=512 (16 warps). warp = 16-channel group; lane owns columns {lane+32j}, j<NPT.
// A loads: uniform broadcast LDS.128 (1 wf). B loads: packed LDS.32 (1 wf). BN = 32*NPT.
template <int NPT>
__global__ void __launch_bounds__(512, 1)
layer_kernel(int pp,
             const float* __restrict__ WdT, const float* __restrict__ bd,
             const float* __restrict__ WrT, const float* __restrict__ br,
             int dil, int u0, int layer) {
    constexpr int BN  = 32 * NPT;
    constexpr int TPB = 512;

    extern __shared__ float smem[];
    float* As0 = smem;                               // 2 x [KT][256]
    float* Bs0 = smem + 2 * KT * RES;                // 2 x [KT][BN]
    float* gs  = smem + 2 * KT * RES + 2 * KT * BN;  // [RES][BN]

    const int tid  = threadIdx.x;
    const int lane = tid & 31;
    const int warp = tid >> 5;
    const int c0   = warp * 16;          // base channel of this warp
    const int b    = blockIdx.y;
    const int ub   = u0 + blockIdx.x * BN;

    const float* hin  = &g_h[pp][b][0][0];
    float*       hout = &g_h[pp ^ 1][b][0][0];

    ull acc[8][NPT];
#pragma unroll
    for (int p = 0; p < 8; p++)
#pragma unroll
        for (int j = 0; j < NPT; j++) acc[p][j] = 0ull;

    // --- staging helpers (cp.async) ---
    auto stageA = [&](int s, const float* src) {      // 32 x 256 floats, contiguous
        float* dstb = As0 + s * KT * RES;
#pragma unroll
        for (int i = tid; i < KT * 64; i += TPB)
            CPA16(su32(dstb + 4 * i), src + 4 * i);
    };
    auto stageB = [&](int s, int k0) {
        float* dstb = Bs0 + s * KT * BN;
#pragma unroll
        for (int e = tid; e < KT * BN; e += TPB) {
            int kr = e / BN, u = e - kr * BN;
            int r  = k0 + kr;
            int ci = r >> 1;
            int off = (r & 1) ? 0 : dil;
            CPA4(su32(dstb + e), hin + ci * HSTR + (ub + u - off));
        }
    };

    // --- compute over one staged k-tile ---
    auto compute = [&](const float* A, const float* B) {
#pragma unroll 8
        for (int kk = 0; kk < KT; kk++) {
            const float* ar = A + kk * RES + c0;      // uniform across lanes -> broadcast
            ulonglong2 q0 = *(const ulonglong2*)(ar);
            ulonglong2 q1 = *(const ulonglong2*)(ar + 4);
            ulonglong2 q2 = *(const ulonglong2*)(ar + 8);
            ulonglong2 q3 = *(const ulonglong2*)(ar + 12);
            ull a2[8] = {q0.x, q0.y, q1.x, q1.y, q2.x, q2.y, q3.x, q3.y};
            ull b2[NPT];
#pragma unroll
            for (int j = 0; j < NPT; j++)
                b2[j] = pk2(B[kk * BN + lane + 32 * j]);   // packed LDS.32
#pragma unroll
            for (int p = 0; p < 8; p++)
#pragma unroll
                for (int j = 0; j < NPT; j++) acc[p][j] = fma2(a2[p], b2[j], acc[p][j]);
        }
    };

    // ---- phase 1: dilated conv, K = 512 (16 tiles) ----
    stageA(0, WdT); stageB(0, 0); CPCOMMIT();
    int cur = 0;
    for (int t = 0; t < 16; t++) {
        CPWAIT0(); __syncthreads();
        if (t + 1 < 16) { stageA(cur ^ 1, WdT + (t + 1) * KT * RES); stageB(cur ^ 1, (t + 1) * KT); }
        else            { stageA(cur ^ 1, WrT); }   // prefetch phase-2 tile 0
        CPCOMMIT();
        compute(As0 + cur * KT * RES, Bs0 + cur * KT * BN);
        cur ^= 1;
    }

    // ---- gate -> gs, skip column extraction, reset acc ----
    {
        int ul   = (WIN - 1) - ub;                  // local column of t = T-1 (if in tile)
        int jown = ul >> 5, lown = ul & 31;
        bool has = (ul >= 0 && ul < BN);
#pragma unroll
        for (int p = 0; p < 8; p++) {
            int co = c0 + 2 * p;
            float bd0 = bd[co], bd1 = bd[co + 1];
#pragma unroll
            for (int j = 0; j < NPT; j++) {
                float2 v = upk(acc[p][j]);
                float g0 = gate_fn(v.x + bd0);
                float g1 = gate_fn(v.y + bd1);
                int col = lane + 32 * j;
                gs[co * BN + col]       = g0;
                gs[(co + 1) * BN + col] = g1;
                if (has && j == jown && lane == lown) {
                    g_gLast[layer][b][co]     = g0;
                    g_gLast[layer][b][co + 1] = g1;
                }
                acc[p][j] = 0ull;
            }
        }
    }

    // ---- phase 2: residual GEMM, K = 256 (8 tiles), B = gs in SMEM ----
    for (int t = 0; t < 8; t++) {
        CPWAIT0(); __syncthreads();    // also publishes gs before first read
        if (t + 1 < 8) stageA(cur ^ 1, WrT + (t + 1) * KT * RES);
        CPCOMMIT();
        compute(As0 + cur * KT * RES, gs + t * KT * BN);
        cur ^= 1;
    }

    // ---- residual epilogue (coalesced: lanes cover 128B per channel row) ----
#pragma unroll
    for (int p = 0; p < 8; p++) {
        int co = c0 + 2 * p;
        float br0 = br[co], br1 = br[co + 1];
#pragma unroll
        for (int j = 0; j < NPT; j++) {
            float2 v = upk(acc[p][j]);
            int uu = ub + lane + 32 * j;
            if (uu < WIN) {
                hout[co * HSTR + uu]       = hin[co * HSTR + uu]       + v.x + br0;
                hout[(co + 1) * HSTR + uu] = hin[(co + 1) * HSTR + uu] + v.y + br1;
            }
        }
    }
}

// ---------------- skip head ----------------
__global__ void skip_kernel(const float* __restrict__ Ws, const float* __restrict__ bs) {
    int b = blockIdx.x;
    int w = threadIdx.x >> 5;
    int lane = threadIdx.x & 31;
    int so_base = blockIdx.y * 64 + w * 8;
    for (int oi = 0; oi < 8; oi++) {
        int so = so_base + oi;
        float v = (lane < NLAY) ? bs[lane * SKIPC + so] : 0.f;
        for (int l = 0; l < NLAY; l++) {
            const float* wr = Ws + ((size_t)l * SKIPC + so) * RES;
            const float* gg = &g_gLast[l][b][0];
#pragma unroll
            for (int k = lane; k < RES; k += 32) v += wr[k] * gg[k];
        }
#pragma unroll
        for (int s = 16; s; s >>= 1) v += __shfl_xor_sync(0xffffffffu, v, s);
        if (lane == 0) g_skip[b][so] = fmaxf(v, 0.f);
    }
}

// ---------------- end head ----------------
__global__ void end_kernel(const float* __restrict__ We1, const float* __restrict__ be1,
                           const float* __restrict__ We2, const float* __restrict__ be2,
                           float* __restrict__ out) {
    __shared__ float sk[SKIPC];
    __shared__ float mid[SKIPC];
    int b = blockIdx.x;
    int tid = threadIdx.x;
    int w = tid >> 5, lane = tid & 31;
    for (int i = tid; i < SKIPC; i += 256) sk[i] = g_skip[b][i];
    __syncthreads();
    for (int oi = 0; oi < 64; oi++) {
        int so = w * 64 + oi;
        const float* row = We1 + (size_t)so * SKIPC;
        float v = 0.f;
#pragma unroll
        for (int k = lane; k < SKIPC; k += 32) v += row[k] * sk[k];
#pragma unroll
        for (int s = 16; s; s >>= 1) v += __shfl_xor_sync(0xffffffffu, v, s);
        if (lane == 0) mid[so] = fmaxf(v + be1[so], 0.f);
    }
    __syncthreads();
    for (int oi = 0; oi < 32; oi++) {
        int nc = w * 32 + oi;
        const float* row = We2 + (size_t)nc * SKIPC;
        float v = 0.f;
#pragma unroll
        for (int k = lane; k < SKIPC; k += 32) v += row[k] * mid[k];
#pragma unroll
        for (int s = 16; s; s >>= 1) v += __shfl_xor_sync(0xffffffffu, v, s);
        if (lane == 0) out[b * NCLSC + nc] = v + be2[nc];
    }
}

// ---------------- host ----------------
static const int DILS[NLAY] = {1,2,4,8,16,32,64,128,256,512,
                               1,2,4,8,16,32,64,128,256,512,
                               1,2,4,8,16,32,64,128,256,512};

static inline size_t smem_for(int BN) {
    return (size_t)(2 * KT * RES + 2 * KT * BN + RES * BN) * sizeof(float);
}

extern "C" void kernel_launch(void* const* d_in, const int* in_sizes, int n_in,
                              void* d_out, int out_size) {
    (void)in_sizes; (void)n_in; (void)out_size;
    const float* x   = (const float*)d_in[0];
    const float* Wst = (const float*)d_in[1];
    const float* bst = (const float*)d_in[2];
    const float* Wd  = (const float*)d_in[3];
    const float* bd  = (const float*)d_in[4];
    const float* Wr  = (const float*)d_in[5];
    const float* br  = (const float*)d_in[6];
    const float* Ws  = (const float*)d_in[7];
    const float* bs  = (const float*)d_in[8];
    const float* We1 = (const float*)d_in[9];
    const float* be1 = (const float*)d_in[10];
    const float* We2 = (const float*)d_in[11];
    const float* be2 = (const float*)d_in[12];
    float* out = (float*)d_out;

    cudaFuncSetAttribute((const void*)layer_kernel<3>, cudaFuncAttributeMaxDynamicSharedMemorySize, (int)smem_for(96));
    cudaFuncSetAttribute((const void*)layer_kernel<2>, cudaFuncAttributeMaxDynamicSharedMemorySize, (int)smem_for(64));
    cudaFuncSetAttribute((const void*)layer_kernel<1>, cudaFuncAttributeMaxDynamicSharedMemorySize, (int)smem_for(32));

    float* wdT_dev; float* wrT_dev;
    cudaGetSymbolAddress((void**)&wdT_dev, g_WdT);
    cudaGetSymbolAddress((void**)&wrT_dev, g_WrT);

    transpose_prep<<<dim3(16, 8, 2 * NLAY), dim3(32, 8)>>>(Wd, Wr);
    start_conv<<<dim3(WIN / 256, Bsz), 256>>>(x, Wst, bst);

    int suf[NLAY + 1];
    suf[NLAY] = 0;
    for (int i = NLAY - 1; i >= 0; i--) suf[i] = suf[i + 1] + DILS[i];

    for (int i = 0; i < NLAY; i++) {
        int N  = 1 + suf[i + 1];
        int u0 = WIN - N;
        int pp = i & 1;
        const float* bdp   = bd + (size_t)i * RES;
        const float* brp   = br + (size_t)i * RES;
        const float* wdt_l = wdT_dev + (size_t)i * 2 * RES * RES;
        const float* wrt_l = wrT_dev + (size_t)i * RES * RES;

        int npt = (N <= 32 * 37) ? 1 : (N <= 64 * 37) ? 2 : 3;
        int BN  = 32 * npt;
        int gx  = (N + BN - 1) / BN;
        dim3 grid(gx, Bsz);
        size_t sm = smem_for(BN);
        switch (npt) {
            case 3: layer_kernel<3><<<grid, 512, sm>>>(pp, wdt_l, bdp, wrt_l, brp, DILS[i], u0, i); break;
            case 2: layer_kernel<2><<<grid, 512, sm>>>(pp, wdt_l, bdp, wrt_l, brp, DILS[i], u0, i); break;
            default: layer_kernel<1><<<grid, 512, sm>>>(pp, wdt_l, bdp, wrt_l, brp, DILS[i], u0, i); break;
        }
    }

    skip_kernel<<<dim3(Bsz, SKIPC / 64), 256>>>(Ws, bs);
    end_kernel<<<Bsz, 256>>>(We1, be1, We2, be2, out);
}